// round 12
// baseline (speedup 1.0000x reference)
#include <cuda_runtime.h>
#include <cuda_bf16.h>
#include <math.h>
#include <stdint.h>

#define MAXN   8192
#define FDIM   128
#define HDIM   512
#define TILE_M 64
#define HSLOTS 16384

#define SXB 136   // bf16 tile row stride (elements); 272B -> ldmatrix conflict-free

typedef unsigned long long ull;

// ---------------- device scratch (no allocations allowed) ------------------
__device__ float g_E[3 * MAXN * FDIM];
__device__ ull   g_hkey[HSLOTS];
__device__ int   g_hcnt[HSLOTS];
__device__ float g_hsum[HSLOTS];
__device__ float g_l2sum;
__device__ float g_ltw;
__device__ int   g_done;
// pre-converted bf16 W tiles in LDSM-ready padded layout
__device__ __nv_bfloat16 g_W1t[4][FDIM][SXB];
__device__ __nv_bfloat16 g_W2t[4][FDIM][SXB];

// ---------------- helpers ---------------------------------------------------
__device__ __forceinline__ uint32_t smem_u32(const void* p) {
    uint32_t a;
    asm("{ .reg .u64 t; cvta.to.shared.u64 t, %1; cvt.u32.u64 %0, t; }" : "=r"(a) : "l"(p));
    return a;
}

#define LDSM4(r0, r1, r2, r3, a) \
    asm volatile("ldmatrix.sync.aligned.m8n8.x4.shared.b16 {%0,%1,%2,%3}, [%4];" \
        : "=r"(r0), "=r"(r1), "=r"(r2), "=r"(r3) : "r"(a))

__device__ __forceinline__ void mma_bf16(float c[4],
                                         uint32_t a0, uint32_t a1, uint32_t a2, uint32_t a3,
                                         uint32_t b0, uint32_t b1) {
    asm volatile("mma.sync.aligned.m16n8k16.row.col.f32.bf16.bf16.f32 "
                 "{%0,%1,%2,%3}, {%4,%5,%6,%7}, {%8,%9}, {%0,%1,%2,%3};"
                 : "+f"(c[0]), "+f"(c[1]), "+f"(c[2]), "+f"(c[3])
                 : "r"(a0), "r"(a1), "r"(a2), "r"(a3), "r"(b0), "r"(b1));
}

__device__ __forceinline__ uint32_t pack_bf2(float x, float y) {
    __nv_bfloat162 b = __floats2bfloat162_rn(x, y);
    return *(uint32_t*)&b;
}

__device__ __forceinline__ void cp16(uint32_t dst, const void* src) {
    asm volatile("cp.async.cg.shared.global [%0], [%1], 16;" :: "r"(dst), "l"(src));
}
#define CP_COMMIT() asm volatile("cp.async.commit_group;" ::: "memory")
#define CP_WAIT(n)  asm volatile("cp.async.wait_group %0;" :: "n"(n) : "memory")

// stage one pre-converted 34816B W tile into SMEM via cp.async (issued async)
__device__ __forceinline__ void stage_cp(uint32_t dst, const __nv_bfloat16* src, int tid) {
    const char* s = (const char*)src;
    #pragma unroll
    for (int j = 0; j < 8; j++)
        cp16(dst + tid * 16 + j * 4096, s + tid * 16 + j * 4096);
    if (tid < 128)
        cp16(dst + tid * 16 + 32768, s + tid * 16 + 32768);
    CP_COMMIT();
}

extern __shared__ __nv_bfloat16 s_b[];

// warp-tile GEMM: 32 rows x 32 cols per warp (2x4 warp grid), K=128
__device__ __forceinline__ void gemm_bf16_tile(float acc[2][4][4],
                                               uint32_t Aaddr0, uint32_t Baddr0) {
    #pragma unroll
    for (int kt = 0; kt < 8; kt++) {
        const uint32_t ko = kt * 32;       // 16 bf16 = 32 bytes per k-step
        uint32_t a[2][4];
        LDSM4(a[0][0], a[0][1], a[0][2], a[0][3], Aaddr0 + ko);
        LDSM4(a[1][0], a[1][1], a[1][2], a[1][3], Aaddr0 + 16 * SXB * 2 + ko);
        uint32_t b[4][2];
        LDSM4(b[0][0], b[0][1], b[1][0], b[1][1], Baddr0 + ko);
        LDSM4(b[2][0], b[2][1], b[3][0], b[3][1], Baddr0 + 16 * SXB * 2 + ko);
        #pragma unroll
        for (int mt = 0; mt < 2; mt++)
            #pragma unroll
            for (int nt = 0; nt < 4; nt++)
                mma_bf16(acc[mt][nt], a[mt][0], a[mt][1], a[mt][2], a[mt][3],
                         b[nt][0], b[nt][1]);
    }
}

// ===========================================================================
// Prep kernel: clear hash table + counters; convert W1/W2 to bf16 tiles
// ===========================================================================
__global__ __launch_bounds__(256)
void prep_kernel(const float* __restrict__ W1, const float* __restrict__ W2)
{
    int t = blockIdx.x * 256 + threadIdx.x;       // 0..16383
    g_hkey[t] = ~0ull;
    g_hcnt[t] = 0;
    g_hsum[t] = 0.f;
    if (t == 0) { g_l2sum = 0.f; g_ltw = 0.f; g_done = 0; }

    int a  = t >> 13;          // 0 = W1, 1 = W2
    int g  = t & 8191;
    int c  = g >> 11;
    int r  = (g >> 4) & 127;
    int kq = (g & 15) * 8;
    const float* src = (a == 0)
        ? W1 + ((size_t)(c * FDIM + r)) * FDIM + kq
        : W2 + (size_t)r * HDIM + c * FDIM + kq;
    float4 v0 = ((const float4*)src)[0];
    float4 v1 = ((const float4*)src)[1];
    uint4 o = make_uint4(pack_bf2(v0.x, v0.y), pack_bf2(v0.z, v0.w),
                         pack_bf2(v1.x, v1.y), pack_bf2(v1.z, v1.w));
    __nv_bfloat16* dst = (a == 0) ? &g_W1t[c][r][kq] : &g_W2t[c][r][kq];
    *(uint4*)dst = o;
}

// ===========================================================================
// Kernel A: gather + renorm + Linear/BN/LeakyReLU/Linear, 64 rows per CTA
// cp.async double-buffered W staging; 3 CTA-wide syncs per chunk (was 4):
// BN (register-only consumer) hoisted before the merged WB0-free/W2-ready sync
// ===========================================================================
__global__ __launch_bounds__(256, 2)
void embed_bf16_kernel(const int* __restrict__ user0, const int* __restrict__ posi,
                       const int* __restrict__ negi,
                       const float* __restrict__ ut, const float* __restrict__ it,
                       const float* __restrict__ b1,
                       const float* __restrict__ gamma1, const float* __restrict__ beta1,
                       const float* __restrict__ rmean, const float* __restrict__ rvar,
                       const float* __restrict__ b2, int N)
{
    const int tid  = threadIdx.x;
    const int wid  = tid >> 5;
    const int lane = tid & 31;
    const int lr   = lane >> 2;      // C-frag row within 16
    const int lq   = lane & 3;       // C-frag col pair
    const int mgg  = wid & 1;        // m group: rows mgg*32
    const int nhh  = wid >> 1;       // n group: cols nhh*32

    __nv_bfloat16* Xs  = s_b;                        // 64*SXB   (17408B)
    __nv_bfloat16* Hs  = Xs + TILE_M * SXB;          // 64*SXB   (17408B)
    __nv_bfloat16* WB0 = Hs + TILE_M * SXB;          // 128*SXB  (34816B)
    __nv_bfloat16* WB1 = WB0 + FDIM * SXB;           // 128*SXB  (34816B)
    float2*        bn  = (float2*)(WB1 + FDIM * SXB);
    float*         sE  = (float*)s_b;                // out staging reuses Xs+Hs

    const int R0 = blockIdx.x * TILE_M;
    const uint32_t wb0 = smem_u32(WB0), wb1 = smem_u32(WB1);

    // kick off the first two W stages immediately
    stage_cp(wb0, &g_W1t[0][0][0], tid);
    stage_cp(wb1, &g_W2t[0][0][0], tid);

    // BN consts (fold b1)
    for (int h = tid; h < HDIM; h += 256) {
        float sc = gamma1[h] * rsqrtf(rvar[h] + 1e-5f);
        bn[h] = make_float2(sc, (b1[h] - rmean[h]) * sc + beta1[h]);
    }

    // X: gather + renorm + bf16 (4 threads per row, 32 cols each)
    {
        int row = tid >> 2;
        int q   = tid & 3;
        int R = R0 + row;
        const float* src = nullptr;
        if (R < 3 * N) {
            int g = R / N, n = R - g * N;
            int idx = (g == 0) ? user0[n] : (g == 1 ? posi[n] : negi[n]);
            src = ((g == 0) ? ut : it) + (size_t)idx * FDIM;
        }
        float4 v[8];
        float ss = 0.f;
        #pragma unroll
        for (int j = 0; j < 8; j++) {
            v[j] = src ? ((const float4*)src)[q * 8 + j] : make_float4(0.f, 0.f, 0.f, 0.f);
            ss += v[j].x * v[j].x + v[j].y * v[j].y + v[j].z * v[j].z + v[j].w * v[j].w;
        }
        ss += __shfl_xor_sync(0xffffffffu, ss, 1);
        ss += __shfl_xor_sync(0xffffffffu, ss, 2);
        float inv = 1.0f / fmaxf(sqrtf(ss), 1.0f);
        #pragma unroll
        for (int j = 0; j < 8; j += 2) {
            uint4 o = make_uint4(pack_bf2(v[j].x * inv, v[j].y * inv),
                                 pack_bf2(v[j].z * inv, v[j].w * inv),
                                 pack_bf2(v[j+1].x * inv, v[j+1].y * inv),
                                 pack_bf2(v[j+1].z * inv, v[j+1].w * inv));
            *(uint4*)(Xs + row * SXB + q * 32 + j * 4) = o;
        }
    }

    // per-thread ldmatrix offsets (bytes)
    const int lg = lane >> 3, lw = lane & 7;
    const uint32_t xb = smem_u32(Xs), hb = smem_u32(Hs);
    const uint32_t aoff = (uint32_t)(((mgg * 32 + (lg & 1) * 8 + lw) * SXB + (lg >> 1) * 8) * 2);
    const uint32_t boff = (uint32_t)(((nhh * 32 + (lg >> 1) * 8 + lw) * SXB + (lg & 1) * 8) * 2);

    float accE[2][4][4];
    #pragma unroll
    for (int i = 0; i < 2; i++)
        #pragma unroll
        for (int j = 0; j < 4; j++)
            #pragma unroll
            for (int k = 0; k < 4; k++) accE[i][j][k] = 0.f;

    #pragma unroll 1
    for (int c = 0; c < 4; c++) {
        // ---- sync 1: W1_c arrived (leaves W2_c pending); also orders
        //      X/Hs hazards (GEMM2(c-1) reads finished before here)
        CP_WAIT(1);
        __syncthreads();

        float acc1[2][4][4];
        #pragma unroll
        for (int i = 0; i < 2; i++)
            #pragma unroll
            for (int j = 0; j < 4; j++)
                #pragma unroll
                for (int k = 0; k < 4; k++) acc1[i][j][k] = 0.f;

        gemm_bf16_tile(acc1, xb + aoff, wb0 + boff);   // reads WB0 + Xs

        // BN + LeakyReLU -> Hs (register-only consumer of acc1; Hs safe:
        // previous chunk's GEMM2 completed before sync 1 above)
        #pragma unroll
        for (int mt = 0; mt < 2; mt++) {
            #pragma unroll
            for (int nt = 0; nt < 4; nt++) {
                int row = mgg * 32 + mt * 16 + lr;
                int col = nhh * 32 + nt * 8 + lq * 2;
                float2 p0 = bn[c * FDIM + col];
                float2 p1 = bn[c * FDIM + col + 1];
                float x0 = acc1[mt][nt][0] * p0.x + p0.y;
                float x1 = acc1[mt][nt][1] * p1.x + p1.y;
                float x2 = acc1[mt][nt][2] * p0.x + p0.y;
                float x3 = acc1[mt][nt][3] * p1.x + p1.y;
                x0 = (x0 >= 0.f) ? x0 : 0.1f * x0;
                x1 = (x1 >= 0.f) ? x1 : 0.1f * x1;
                x2 = (x2 >= 0.f) ? x2 : 0.1f * x2;
                x3 = (x3 >= 0.f) ? x3 : 0.1f * x3;
                *(uint32_t*)(Hs + row * SXB + col)       = pack_bf2(x0, x1);
                *(uint32_t*)(Hs + (row + 8) * SXB + col) = pack_bf2(x2, x3);
            }
        }

        // ---- sync 2 (merged): all WB0 reads done + W2_c arrived + Hs visible
        CP_WAIT(0);
        __syncthreads();

        if (c < 3) stage_cp(wb0, &g_W1t[c + 1][0][0], tid);   // refill WB0 (async, overlaps GEMM2)

        gemm_bf16_tile(accE, hb + aoff, wb1 + boff);   // reads WB1 + Hs

        // ---- sync 3: all WB1 reads done before refill
        __syncthreads();

        if (c < 3) stage_cp(wb1, &g_W2t[c + 1][0][0], tid);   // refill WB1
    }

    // E -> padded SMEM -> coalesced global write (+ b2)
    #pragma unroll
    for (int mt = 0; mt < 2; mt++) {
        #pragma unroll
        for (int nt = 0; nt < 4; nt++) {
            int row = mgg * 32 + mt * 16 + lr;
            int col = nhh * 32 + nt * 8 + lq * 2;
            *(float2*)(sE + row * 130 + col)       = make_float2(accE[mt][nt][0], accE[mt][nt][1]);
            *(float2*)(sE + (row + 8) * 130 + col) = make_float2(accE[mt][nt][2], accE[mt][nt][3]);
        }
    }
    __syncthreads();
    for (int i = tid; i < TILE_M * FDIM; i += 256) {
        int row = i >> 7, col = i & 127;
        int R = R0 + row;
        if (R < 3 * N) g_E[(size_t)R * FDIM + col] = sE[row * 130 + col] + b2[col];
    }
}

// ===========================================================================
// Kernel B: one warp per sample -> distances, L2 sum, per-slot (cnt, sum_lt).
// Only samples with lt>0 touch the hash table (lt=0 contributes 0 to both).
// ===========================================================================
__global__ __launch_bounds__(256)
void dist_hash_kernel(const int* __restrict__ user0, const int* __restrict__ posi, int N)
{
    int gw = (blockIdx.x * 256 + threadIdx.x) >> 5;
    int l = threadIdx.x & 31;
    float dp = 0.f, dn = 0.f, l2 = 0.f;
    if (gw < N) {
        float4 a = *((const float4*)g_E + (size_t)gw * 32 + l);
        float4 p = *((const float4*)g_E + (size_t)(N + gw) * 32 + l);
        float4 q = *((const float4*)g_E + (size_t)(2 * N + gw) * 32 + l);
        float d;
        d = a.x - p.x; dp += d * d; d = a.y - p.y; dp += d * d;
        d = a.z - p.z; dp += d * d; d = a.w - p.w; dp += d * d;
        d = a.x - q.x; dn += d * d; d = a.y - q.y; dn += d * d;
        d = a.z - q.z; dn += d * d; d = a.w - q.w; dn += d * d;
        l2 += a.x * a.x + a.y * a.y + a.z * a.z + a.w * a.w;
        l2 += p.x * p.x + p.y * p.y + p.z * p.z + p.w * p.w;
        l2 += q.x * q.x + q.y * q.y + q.z * q.z + q.w * q.w;
    }
    #pragma unroll
    for (int s = 16; s >= 1; s >>= 1) {
        dp += __shfl_xor_sync(0xffffffffu, dp, s);
        dn += __shfl_xor_sync(0xffffffffu, dn, s);
        l2 += __shfl_xor_sync(0xffffffffu, l2, s);
    }
    __shared__ float sl2[8];
    if (l == 0) {
        if (gw < N) {
            float lt = fmaxf(dp - dn + 0.5f, 0.f);
            if (lt > 0.f) {
                ull key = ((ull)(unsigned)user0[gw] << 17) | ((ull)(unsigned)posi[gw]);
                uint32_t slot = (uint32_t)((key * 0x9E3779B97F4A7C15ull) >> 50);
                for (;;) {
                    ull old = atomicCAS(&g_hkey[slot], ~0ull, key);
                    if (old == ~0ull || old == key) {
                        atomicAdd(&g_hcnt[slot], 1);
                        atomicAdd(&g_hsum[slot], lt);
                        break;
                    }
                    slot = (slot + 1) & (HSLOTS - 1);
                }
            }
        }
        sl2[threadIdx.x >> 5] = l2;
    }
    __syncthreads();
    if (threadIdx.x == 0) {
        float s = 0.f;
        #pragma unroll
        for (int i = 0; i < 8; i++) s += sl2[i];
        atomicAdd(&g_l2sum, s);
    }
}

// ===========================================================================
// Kernel C: flat slot scan -> sum w(M)*sum_lt; last-block finalize
// ===========================================================================
__global__ __launch_bounds__(256)
void weight_finalize_kernel(const int* __restrict__ Jp, const int* __restrict__ Up,
                            int N, float* __restrict__ out)
{
    int i = blockIdx.x * 256 + threadIdx.x;     // 0..HSLOTS-1
    int   M = g_hcnt[i];
    float s = g_hsum[i];
    int J = *Jp, U = *Up;
    float contrib = 0.f;
    if (M > 0 && U > 0)
        contrib = s * logf((float)J * (float)M / (float)U + 1.0f);

    #pragma unroll
    for (int sft = 16; sft >= 1; sft >>= 1)
        contrib += __shfl_xor_sync(0xffffffffu, contrib, sft);
    __shared__ float sw[8];
    if ((threadIdx.x & 31) == 0) sw[threadIdx.x >> 5] = contrib;
    __syncthreads();
    if (threadIdx.x == 0) {
        float acc = 0.f;
        #pragma unroll
        for (int k = 0; k < 8; k++) acc += sw[k];
        atomicAdd(&g_ltw, acc);
        __threadfence();
        int prev = atomicAdd(&g_done, 1);
        if (prev == (int)gridDim.x - 1) {
            float ltw = atomicAdd(&g_ltw, 0.f);
            float l2  = atomicAdd(&g_l2sum, 0.f);
            float ltm = ltw / (float)N;
            out[1] = ltm;
            out[0] = ltm + 1e-3f * l2 / (float)N;
            g_done = 0;
        }
    }
}

// ===========================================================================
extern "C" void kernel_launch(void* const* d_in, const int* in_sizes, int n_in,
                              void* d_out, int out_size)
{
    const int*   user0 = (const int*)d_in[0];
    const int*   posi  = (const int*)d_in[1];
    const int*   negi  = (const int*)d_in[2];
    // d_in[3] = ratings (unused)
    const float* ut = (const float*)d_in[4];
    const float* it = (const float*)d_in[5];
    const float* W1 = (const float*)d_in[6];
    const float* b1 = (const float*)d_in[7];
    const float* ga = (const float*)d_in[8];
    const float* be = (const float*)d_in[9];
    const float* rm = (const float*)d_in[10];
    const float* rv = (const float*)d_in[11];
    const float* W2 = (const float*)d_in[12];
    const float* b2 = (const float*)d_in[13];
    const int*   Jp = (const int*)d_in[14];
    const int*   Up = (const int*)d_in[15];
    int N = in_sizes[0];
    if (N > MAXN) N = MAXN;

    // SMEM: Xs + Hs (64 rows) + WB0 + WB1 (128 rows) + bn = 108544 B
    const int smemA = (2 * TILE_M + 2 * FDIM) * SXB * 2 + HDIM * 8;
    cudaFuncSetAttribute(embed_bf16_kernel, cudaFuncAttributeMaxDynamicSharedMemorySize, smemA);

    prep_kernel<<<HSLOTS / 256, 256>>>(W1, W2);
    int blocksA = (3 * N + TILE_M - 1) / TILE_M;
    embed_bf16_kernel<<<blocksA, 256, smemA>>>(user0, posi, negi, ut, it,
                                               b1, ga, be, rm, rv, b2, N);
    dist_hash_kernel<<<(N + 7) / 8, 256>>>(user0, posi, N);
    weight_finalize_kernel<<<HSLOTS / 256, 256>>>(Jp, Up, N, (float*)d_out);
}